// round 2
// baseline (speedup 1.0000x reference)
#include <cuda_runtime.h>

// out[i] = -0.1f * v[i] over N*D = 200000 floats (zero-potential edge pipeline
// contributes exactly 0; see R0 derivation).
//
// R2 change: per-thread MLP=4. Each thread issues 4 independent LDG.128
// (front-batched by ptxas), overlapping memory latency 4x vs the R1
// one-load-per-thread version. 98 blocks x 128 threads x 4 float4 = 50176
// slots covering n4 = 50000.

#define GAMMA 0.1f

__global__ void __launch_bounds__(128) scale_v_kernel(const float4* __restrict__ v4,
                                                      float4* __restrict__ out4,
                                                      int n4) {
    const int stride = 128;                       // blockDim.x
    int base = blockIdx.x * (stride * 4) + threadIdx.x;

    int i0 = base;
    int i1 = base + stride;
    int i2 = base + 2 * stride;
    int i3 = base + 3 * stride;

    bool p0 = i0 < n4, p1 = i1 < n4, p2 = i2 < n4, p3 = i3 < n4;

    float4 a0, a1, a2, a3;
    // Front-batched independent loads (MLP=4); predicated so the partial
    // tail block is safe.
    if (p0) a0 = v4[i0];
    if (p1) a1 = v4[i1];
    if (p2) a2 = v4[i2];
    if (p3) a3 = v4[i3];

    if (p0) { float4 r = {-GAMMA*a0.x, -GAMMA*a0.y, -GAMMA*a0.z, -GAMMA*a0.w}; out4[i0] = r; }
    if (p1) { float4 r = {-GAMMA*a1.x, -GAMMA*a1.y, -GAMMA*a1.z, -GAMMA*a1.w}; out4[i1] = r; }
    if (p2) { float4 r = {-GAMMA*a2.x, -GAMMA*a2.y, -GAMMA*a2.z, -GAMMA*a2.w}; out4[i2] = r; }
    if (p3) { float4 r = {-GAMMA*a3.x, -GAMMA*a3.y, -GAMMA*a3.z, -GAMMA*a3.w}; out4[i3] = r; }
}

// Tail safety for out_size % 4 != 0 (not hit for this shape).
__global__ void scale_v_tail_kernel(const float* __restrict__ v,
                                    float* __restrict__ out,
                                    int start, int n) {
    int i = start + blockIdx.x * blockDim.x + threadIdx.x;
    if (i < n) out[i] = -GAMMA * v[i];
}

extern "C" void kernel_launch(void* const* d_in, const int* in_sizes, int n_in,
                              void* d_out, int out_size) {
    // metadata order: x, v, src, dst
    const float* v = (const float*)d_in[1];
    float* out = (float*)d_out;

    int n = out_size;      // 200000
    int n4 = n / 4;        // 50000
    int tail = n - n4 * 4;

    const int TPB = 128;
    const int PER_BLOCK = TPB * 4;  // 512 float4 per block
    if (n4 > 0) {
        int blocks = (n4 + PER_BLOCK - 1) / PER_BLOCK;   // 98
        scale_v_kernel<<<blocks, TPB>>>((const float4*)v, (float4*)out, n4);
    }
    if (tail > 0) {
        int blocks = (tail + 255) / 256;
        scale_v_tail_kernel<<<blocks, 256>>>(v, out, n4 * 4, n);
    }
}

// round 3
// speedup vs baseline: 1.0214x; 1.0214x over previous
#include <cuda_runtime.h>

// out[i] = -0.1f * v[i] over N*D = 200000 floats (zero-potential edge pipeline
// contributes exactly 0; see R0 derivation).
//
// R3 change: single-wave grid. 98 blocks x 512 threads = 50176 threads, one
// float4 each (covers n4=50000), all blocks resident in one wave on 148 SMs.
// Removes R1's partial second wave (196 CTAs -> 48 SMs ran 2 CTAs serially),
// keeps the minimal 1-LDG.128 -> 1-STG.128 per-thread critical path.

#define GAMMA 0.1f

__global__ void __launch_bounds__(512) scale_v_kernel(const float4* __restrict__ v4,
                                                      float4* __restrict__ out4,
                                                      int n4) {
    int i = blockIdx.x * 512 + threadIdx.x;
    if (i < n4) {
        float4 a = v4[i];
        float4 r;
        r.x = -GAMMA * a.x;
        r.y = -GAMMA * a.y;
        r.z = -GAMMA * a.z;
        r.w = -GAMMA * a.w;
        out4[i] = r;
    }
}

// Tail safety for out_size % 4 != 0 (not hit for this shape).
__global__ void scale_v_tail_kernel(const float* __restrict__ v,
                                    float* __restrict__ out,
                                    int start, int n) {
    int i = start + blockIdx.x * blockDim.x + threadIdx.x;
    if (i < n) out[i] = -GAMMA * v[i];
}

extern "C" void kernel_launch(void* const* d_in, const int* in_sizes, int n_in,
                              void* d_out, int out_size) {
    // metadata order: x, v, src, dst
    const float* v = (const float*)d_in[1];
    float* out = (float*)d_out;

    int n = out_size;      // 200000
    int n4 = n / 4;        // 50000
    int tail = n - n4 * 4;

    const int TPB = 512;
    if (n4 > 0) {
        int blocks = (n4 + TPB - 1) / TPB;   // 98 -> single wave on 148 SMs
        scale_v_kernel<<<blocks, TPB>>>((const float4*)v, (float4*)out, n4);
    }
    if (tail > 0) {
        int blocks = (tail + 255) / 256;
        scale_v_tail_kernel<<<blocks, 256>>>(v, out, n4 * 4, n);
    }
}

// round 4
// speedup vs baseline: 1.1790x; 1.1543x over previous
#include <cuda_runtime.h>

// out[i] = -0.1f * v[i] over N*D = 200000 floats (zero-potential edge pipeline
// contributes exactly 0; see R0 derivation).
//
// R4 change: sm_100a 256-bit global ld/st (ld.global.v8.f32 -> LDG.E.256).
// 98 blocks x 256 threads = 25088 threads, one 32B load + one 32B store each
// (covers n8 = 25000). Halves LDG/STG wavefront count vs float4; single wave.

#define GAMMA 0.1f

struct __align__(32) f8 { float v[8]; };

__global__ void __launch_bounds__(256) scale_v_kernel(const float* __restrict__ v,
                                                      float* __restrict__ out,
                                                      int n8) {
    int i = blockIdx.x * 256 + threadIdx.x;
    if (i < n8) {
        const float* src = v + (size_t)i * 8;
        float* dst = out + (size_t)i * 8;
        float a0, a1, a2, a3, a4, a5, a6, a7;
        asm volatile(
            "ld.global.v8.f32 {%0,%1,%2,%3,%4,%5,%6,%7}, [%8];"
            : "=f"(a0), "=f"(a1), "=f"(a2), "=f"(a3),
              "=f"(a4), "=f"(a5), "=f"(a6), "=f"(a7)
            : "l"(src));
        a0 = -GAMMA * a0; a1 = -GAMMA * a1; a2 = -GAMMA * a2; a3 = -GAMMA * a3;
        a4 = -GAMMA * a4; a5 = -GAMMA * a5; a6 = -GAMMA * a6; a7 = -GAMMA * a7;
        asm volatile(
            "st.global.v8.f32 [%0], {%1,%2,%3,%4,%5,%6,%7,%8};"
            :: "l"(dst),
               "f"(a0), "f"(a1), "f"(a2), "f"(a3),
               "f"(a4), "f"(a5), "f"(a6), "f"(a7)
            : "memory");
    }
}

// Tail safety for out_size % 8 != 0 (not hit for this shape: 200000 % 8 == 0).
__global__ void scale_v_tail_kernel(const float* __restrict__ v,
                                    float* __restrict__ out,
                                    int start, int n) {
    int i = start + blockIdx.x * blockDim.x + threadIdx.x;
    if (i < n) out[i] = -GAMMA * v[i];
}

extern "C" void kernel_launch(void* const* d_in, const int* in_sizes, int n_in,
                              void* d_out, int out_size) {
    // metadata order: x, v, src, dst
    const float* v = (const float*)d_in[1];
    float* out = (float*)d_out;

    int n = out_size;      // 200000
    int n8 = n / 8;        // 25000
    int tail = n - n8 * 8; // 0 for this shape

    const int TPB = 256;
    if (n8 > 0) {
        int blocks = (n8 + TPB - 1) / TPB;   // 98 -> single wave on 148 SMs
        scale_v_kernel<<<blocks, TPB>>>(v, out, n8);
    }
    if (tail > 0) {
        int blocks = (tail + 255) / 256;
        scale_v_tail_kernel<<<blocks, 256>>>(v, out, n8 * 8, n);
    }
}

// round 6
// speedup vs baseline: 1.1938x; 1.0125x over previous
#include <cuda_runtime.h>

// out[i] = -0.1f * v[i] over N*D = 200000 floats (zero-potential edge pipeline
// contributes exactly 0; see R0 derivation).
//
// R5 retry (previous bench was an infra failure — container died, no data):
// keep R4's 256-bit ld/st (the proven win axis: wavefront count), halve CTA
// count (49 blocks x 512 threads = 25088 threads, one v8 per thread),
// read-only .nc load path. Single wave; predicated tail inside the last
// block (n8 = 25000 < 25088).

#define GAMMA 0.1f

__global__ void __launch_bounds__(512) scale_v_kernel(const float* __restrict__ v,
                                                      float* __restrict__ out,
                                                      int n8) {
    int i = blockIdx.x * 512 + threadIdx.x;
    if (i < n8) {
        const float* src = v + (size_t)i * 8;
        float* dst = out + (size_t)i * 8;
        float a0, a1, a2, a3, a4, a5, a6, a7;
        asm volatile(
            "ld.global.nc.v8.f32 {%0,%1,%2,%3,%4,%5,%6,%7}, [%8];"
            : "=f"(a0), "=f"(a1), "=f"(a2), "=f"(a3),
              "=f"(a4), "=f"(a5), "=f"(a6), "=f"(a7)
            : "l"(src));
        a0 = -GAMMA * a0; a1 = -GAMMA * a1; a2 = -GAMMA * a2; a3 = -GAMMA * a3;
        a4 = -GAMMA * a4; a5 = -GAMMA * a5; a6 = -GAMMA * a6; a7 = -GAMMA * a7;
        asm volatile(
            "st.global.v8.f32 [%0], {%1,%2,%3,%4,%5,%6,%7,%8};"
            :: "l"(dst),
               "f"(a0), "f"(a1), "f"(a2), "f"(a3),
               "f"(a4), "f"(a5), "f"(a6), "f"(a7)
            : "memory");
    }
}

// Tail safety for out_size % 8 != 0 (not hit for this shape: 200000 % 8 == 0).
__global__ void scale_v_tail_kernel(const float* __restrict__ v,
                                    float* __restrict__ out,
                                    int start, int n) {
    int i = start + blockIdx.x * blockDim.x + threadIdx.x;
    if (i < n) out[i] = -GAMMA * v[i];
}

extern "C" void kernel_launch(void* const* d_in, const int* in_sizes, int n_in,
                              void* d_out, int out_size) {
    // metadata order: x, v, src, dst
    const float* v = (const float*)d_in[1];
    float* out = (float*)d_out;

    int n = out_size;      // 200000
    int n8 = n / 8;        // 25000
    int tail = n - n8 * 8; // 0 for this shape

    const int TPB = 512;
    if (n8 > 0) {
        int blocks = (n8 + TPB - 1) / TPB;   // 49 -> single wave
        scale_v_kernel<<<blocks, TPB>>>(v, out, n8);
    }
    if (tail > 0) {
        int blocks = (tail + 255) / 256;
        scale_v_tail_kernel<<<blocks, 256>>>(v, out, n8 * 8, n);
    }
}

// round 9
// speedup vs baseline: 1.2089x; 1.0127x over previous
#include <cuda_runtime.h>

// out[i] = -0.1f * v[i] over N*D = 200000 floats (zero-potential edge pipeline
// contributes exactly 0; see R0 derivation: force = ||dr||*0.0 == 0.0 for all
// finite dr, messages are exact zeros, segment_sum of zeros is zero, so
// a = -GAMMA * v elementwise).
//
// R8 = revert to the measured-best R5 (dur 5.12us, passed): the R6/R7
// predicate-removal variant hit broker infra failures twice and its predicted
// upside (<=0.05us) is below measurement noise — not worth further retries.
// Kernel: 49 blocks x 512 threads = 25088 threads, one 256-bit load + one
// 256-bit store each (n8 = 25000), single CTA wave, read-only .nc load path.

#define GAMMA 0.1f

__global__ void __launch_bounds__(512) scale_v_kernel(const float* __restrict__ v,
                                                      float* __restrict__ out,
                                                      int n8) {
    int i = blockIdx.x * 512 + threadIdx.x;
    if (i < n8) {
        const float* src = v + (size_t)i * 8;
        float* dst = out + (size_t)i * 8;
        float a0, a1, a2, a3, a4, a5, a6, a7;
        asm volatile(
            "ld.global.nc.v8.f32 {%0,%1,%2,%3,%4,%5,%6,%7}, [%8];"
            : "=f"(a0), "=f"(a1), "=f"(a2), "=f"(a3),
              "=f"(a4), "=f"(a5), "=f"(a6), "=f"(a7)
            : "l"(src));
        a0 = -GAMMA * a0; a1 = -GAMMA * a1; a2 = -GAMMA * a2; a3 = -GAMMA * a3;
        a4 = -GAMMA * a4; a5 = -GAMMA * a5; a6 = -GAMMA * a6; a7 = -GAMMA * a7;
        asm volatile(
            "st.global.v8.f32 [%0], {%1,%2,%3,%4,%5,%6,%7,%8};"
            :: "l"(dst),
               "f"(a0), "f"(a1), "f"(a2), "f"(a3),
               "f"(a4), "f"(a5), "f"(a6), "f"(a7)
            : "memory");
    }
}

// Tail safety for out_size % 8 != 0 (not hit for this shape: 200000 % 8 == 0).
__global__ void scale_v_tail_kernel(const float* __restrict__ v,
                                    float* __restrict__ out,
                                    int start, int n) {
    int i = start + blockIdx.x * blockDim.x + threadIdx.x;
    if (i < n) out[i] = -GAMMA * v[i];
}

extern "C" void kernel_launch(void* const* d_in, const int* in_sizes, int n_in,
                              void* d_out, int out_size) {
    // metadata order: x, v, src, dst
    const float* v = (const float*)d_in[1];
    float* out = (float*)d_out;

    int n = out_size;      // 200000
    int n8 = n / 8;        // 25000
    int tail = n - n8 * 8; // 0 for this shape

    const int TPB = 512;
    if (n8 > 0) {
        int blocks = (n8 + TPB - 1) / TPB;   // 49 -> single wave
        scale_v_kernel<<<blocks, TPB>>>(v, out, n8);
    }
    if (tail > 0) {
        int blocks = (tail + 255) / 256;
        scale_v_tail_kernel<<<blocks, 256>>>(v, out, n8 * 8, n);
    }
}